// round 14
// baseline (speedup 1.0000x reference)
#include <cuda_runtime.h>
#include <cuda_fp16.h>
#include <math.h>
#include <stdint.h>

// ----------------------------------------------------------------------------
// Dnn_with_Attention on sm_103 (family-generic: mma.sync HMMA path).
// Pure fp16 operands, fp32 accumulate. 128x128 CTA tile, 64x64 warp tiles,
// 4 warps / 128 threads per CTA, 2 CTAs/SM, BKC=64, 3-stage cp.async.
// R14: k-column-sliced quarter loads + one commit group PER SLICE with
// per-slice wait_group 8 — each k16 slice waits only for its own quarter
// (issued 8 slices earlier), eliminating the chunk-wide arrival coupling.
// W5 attention-logit GEMV fused into layer-4 epilogue.
// ----------------------------------------------------------------------------

#define TOTAL_N 131072
#define HID     1024
#define FEAT    78
#define K1P     128
#define NSEG    256
#define NCLS    10

#define BM 128
#define BN 128
#define BKC 64                        // K elems per chunk (128 bytes/row)
#define STAGES 3
#define ROWB 144                      // 128B data + 16B pad (conflict-free)
#define A_BYTES (BM * ROWB)           // 18432
#define B_BYTES (BN * ROWB)           // 18432
#define STAGE_BYTES (A_BYTES + B_BYTES)        // 36864
#define GEMM_SMEM (STAGES * STAGE_BYTES)       // 110592

typedef __half f16;

// ------------------------------- scratch -----------------------------------
__device__ f16 g_xp[(size_t)TOTAL_N * K1P];
__device__ f16 g_A[(size_t)TOTAL_N * HID];
__device__ f16 g_B[(size_t)TOTAL_N * HID];
__device__ f16 g_W1t[HID * K1P];
__device__ f16 g_Wt[3][HID * HID];
__device__ float g_scores_raw[TOTAL_N];
__device__ float g_pooled[NSEG * HID];
__device__ float g_tmp6[NSEG * HID];

// ------------------------------ helpers ------------------------------------
__device__ __forceinline__ uint32_t smem_u32(const void* p) {
    uint32_t a;
    asm("{ .reg .u64 t; cvta.to.shared.u64 t, %1; cvt.u32.u64 %0, t; }"
        : "=r"(a) : "l"(p));
    return a;
}
__device__ __forceinline__ void cp16(uint32_t dst, const void* src) {
    asm volatile("cp.async.cg.shared.global [%0], [%1], 16;"
                 :: "r"(dst), "l"(src) : "memory");
}
__device__ __forceinline__ void cp_commit() {
    asm volatile("cp.async.commit_group;" ::: "memory");
}
template <int N>
__device__ __forceinline__ void cp_wait() {
    asm volatile("cp.async.wait_group %0;" :: "n"(N) : "memory");
}
__device__ __forceinline__ void ldmx4(uint32_t* r, uint32_t addr) {
    asm volatile("ldmatrix.sync.aligned.m8n8.x4.shared.b16 {%0,%1,%2,%3}, [%4];"
                 : "=r"(r[0]), "=r"(r[1]), "=r"(r[2]), "=r"(r[3]) : "r"(addr));
}
__device__ __forceinline__ void mma_f16(float* c, const uint32_t* a,
                                        const uint32_t* b) {
    asm volatile(
        "mma.sync.aligned.m16n8k16.row.col.f32.f16.f16.f32 "
        "{%0,%1,%2,%3}, {%4,%5,%6,%7}, {%8,%9}, {%0,%1,%2,%3};"
        : "+f"(c[0]), "+f"(c[1]), "+f"(c[2]), "+f"(c[3])
        : "r"(a[0]), "r"(a[1]), "r"(a[2]), "r"(a[3]), "r"(b[0]), "r"(b[1]));
}

// ----------------------------------------------------------------------------
// HMMA GEMM: C[M,1024] = relu(A[M,K] @ Bt[1024,K]^T + bias), fp16 in, fp32 acc.
// Optional fused W5 dots -> atomicAdd(scores_raw) (layer 4).
// grid = (1024/BN, M/BM), block = 128 (4 warps, each 64x64), 2 CTAs/SM.
// ----------------------------------------------------------------------------
__global__ void __launch_bounds__(128, 2) gemm_mma_kernel(
    const f16* __restrict__ A, const f16* __restrict__ Bt,
    const float* __restrict__ bias, f16* __restrict__ C,
    const float* __restrict__ W5, float* __restrict__ scores_raw,
    int K)
{
    extern __shared__ char smem[];
    const uint32_t sbase = smem_u32(smem);
    const int tid = threadIdx.x;
    const int lane = tid & 31;
    const int wid = tid >> 5;
    const int wm = (wid >> 1) * 64;    // 2 warps over m
    const int wn = (wid & 1) * 64;     // 2 warps over n
    const int m0 = blockIdx.y * BM;
    const int n0 = blockIdx.x * BN;
    const int NC = K / BKC;

    // ldmatrix lane-address components
    const int a_row = lane & 15;
    const int a_kb  = (lane >> 4) * 16;
    const int b_row = (lane & 7) + 8 * (lane >> 4);
    const int b_kb  = ((lane >> 3) & 1) * 16;

    float acc[4][8][4];
    #pragma unroll
    for (int i = 0; i < 4; i++)
        #pragma unroll
        for (int j = 0; j < 8; j++)
            #pragma unroll
            for (int q = 0; q < 4; q++) acc[i][j][q] = 0.f;

    // k-column quarter loader: quarter q covers c16 in {2q, 2q+1}, all rows.
    // Each thread: row = tid, 2x16B (one 32B sector) per matrix. 4 cp16/thread.
    auto load_quarter = [&](int stage, int kc, int q) {
        const uint32_t sd = sbase + stage * STAGE_BYTES;
        const int k0 = kc * BKC;
        const int cb = q * 32;                 // byte offset of this k16 slice
        const uint32_t soA = sd + tid * ROWB + cb;
        const f16* gA = A + (size_t)(m0 + tid) * K + k0 + q * 16;
        cp16(soA,      gA);
        cp16(soA + 16, gA + 8);
        const uint32_t soB = sd + A_BYTES + tid * ROWB + cb;
        const f16* gB = Bt + (size_t)(n0 + tid) * K + k0 + q * 16;
        cp16(soB,      gB);
        cp16(soB + 16, gB + 8);
    };

    // prologue: chunks 0..STAGES-2, one commit group per quarter (8 groups).
    // NC >= 2 always holds (K is 128 or 1024).
    #pragma unroll
    for (int c = 0; c < STAGES - 1; ++c) {
        #pragma unroll
        for (int q = 0; q < 4; ++q) {
            load_quarter(c, c, q);
            cp_commit();
        }
    }

    for (int c = 0; c < NC; ++c) {
        __syncthreads();   // all warps done reading stage (c+2)%3 (chunk c-1)

        const int lc = c + STAGES - 1;
        const int lstage = lc % STAGES;
        const bool do_load = (lc < NC);

        const uint32_t st = sbase + (c % STAGES) * STAGE_BYTES;
        #pragma unroll
        for (int k16 = 0; k16 < 4; ++k16) {
            // issue quarter k16 of chunk c+2 (or an empty group, keeping the
            // per-slice group count uniform so wait_group<8> is exact)
            if (do_load) load_quarter(lstage, lc, k16);
            cp_commit();
            // quarter (c, k16) was committed exactly 9 groups ago
            cp_wait<8>();

            const int xb = k16 * 32;
            uint32_t a[4][4], b[8][2];
            #pragma unroll
            for (int mf = 0; mf < 4; ++mf)
                ldmx4(a[mf], st + (wm + mf * 16 + a_row) * ROWB + xb + a_kb);
            #pragma unroll
            for (int p = 0; p < 4; ++p) {
                uint32_t r[4];
                ldmx4(r, st + A_BYTES +
                          (wn + p * 16 + b_row) * ROWB + xb + b_kb);
                b[p * 2][0] = r[0]; b[p * 2][1] = r[1];
                b[p * 2 + 1][0] = r[2]; b[p * 2 + 1][1] = r[3];
            }
            #pragma unroll
            for (int mf = 0; mf < 4; ++mf)
                #pragma unroll
                for (int nf = 0; nf < 8; ++nf)
                    mma_f16(acc[mf][nf], a[mf], b[nf]);
        }
    }

    // epilogue: bias + relu + fp16 store (+ fused W5 dot)
    const int gr = lane >> 2;
    float sdot[4][2];
    #pragma unroll
    for (int mf = 0; mf < 4; ++mf) { sdot[mf][0] = 0.f; sdot[mf][1] = 0.f; }

    #pragma unroll
    for (int mf = 0; mf < 4; ++mf) {
        const int r0 = m0 + wm + mf * 16 + gr;
        #pragma unroll
        for (int nf = 0; nf < 8; ++nf) {
            const int c0 = n0 + wn + nf * 8 + (lane & 3) * 2;
            const float bv0 = bias[c0], bv1 = bias[c0 + 1];
            const float v00 = fmaxf(acc[mf][nf][0] + bv0, 0.f);
            const float v01 = fmaxf(acc[mf][nf][1] + bv1, 0.f);
            const float v10 = fmaxf(acc[mf][nf][2] + bv0, 0.f);
            const float v11 = fmaxf(acc[mf][nf][3] + bv1, 0.f);

            if (W5 != nullptr) {
                const float w0 = W5[c0], w1 = W5[c0 + 1];
                sdot[mf][0] = fmaf(v00, w0, fmaf(v01, w1, sdot[mf][0]));
                sdot[mf][1] = fmaf(v10, w0, fmaf(v11, w1, sdot[mf][1]));
            }

            const uint32_t p0 =
                ((uint32_t)__half_as_ushort(__float2half(v01)) << 16) |
                __half_as_ushort(__float2half(v00));
            const uint32_t p1 =
                ((uint32_t)__half_as_ushort(__float2half(v11)) << 16) |
                __half_as_ushort(__float2half(v10));
            *reinterpret_cast<uint32_t*>(C + (size_t)r0 * HID + c0) = p0;
            *reinterpret_cast<uint32_t*>(C + (size_t)(r0 + 8) * HID + c0) = p1;
        }
    }

    if (W5 != nullptr) {
        #pragma unroll
        for (int mf = 0; mf < 4; ++mf) {
            float s0 = sdot[mf][0], s1 = sdot[mf][1];
            s0 += __shfl_xor_sync(0xffffffffu, s0, 1);
            s0 += __shfl_xor_sync(0xffffffffu, s0, 2);
            s1 += __shfl_xor_sync(0xffffffffu, s1, 1);
            s1 += __shfl_xor_sync(0xffffffffu, s1, 2);
            if ((lane & 3) == 0) {
                const int r0 = m0 + wm + mf * 16 + gr;
                atomicAdd(&scores_raw[r0], s0);
                atomicAdd(&scores_raw[r0 + 8], s1);
            }
        }
    }
}

// ----------------------------------------------------------------------------
// Prep kernels (convert_x also zeroes scores_raw)
// ----------------------------------------------------------------------------
__global__ __launch_bounds__(256) void convert_x_kernel(
    const float* __restrict__ x, f16* __restrict__ xp,
    float* __restrict__ scores_raw)
{
    const size_t idx = (size_t)blockIdx.x * 256 + threadIdx.x;
    const int row = (int)(idx >> 7);
    const int k = (int)(idx & 127);
    xp[idx] = __float2half((k < FEAT) ? x[(size_t)row * FEAT + k] : 0.f);
    if (k == 0) scores_raw[row] = 0.f;
}

__global__ __launch_bounds__(256) void transpose_w_kernel(
    const float* __restrict__ W, int Kin, int Kpad, f16* __restrict__ Wt)
{
    __shared__ float t[32][33];
    const int n0 = blockIdx.x * 32;
    const int k0 = blockIdx.y * 32;
    #pragma unroll
    for (int r = 0; r < 4; ++r) {
        const int k = k0 + threadIdx.y + r * 8;
        t[threadIdx.y + r * 8][threadIdx.x] =
            (k < Kin) ? W[(size_t)k * HID + n0 + threadIdx.x] : 0.f;
    }
    __syncthreads();
    #pragma unroll
    for (int r = 0; r < 4; ++r) {
        const int n = n0 + threadIdx.y + r * 8;
        const int k = k0 + threadIdx.x;
        Wt[(size_t)n * Kpad + k] = __float2half(t[threadIdx.x][threadIdx.y + r * 8]);
    }
}

// ----------------------------------------------------------------------------
// Ragged segment softmax + weighted pooling. score_i = relu(raw_i + b5).
// One block per segment, 512 threads, 2 dims/thread (half2), smem weight cache.
// ----------------------------------------------------------------------------
#define WCAP 2048

__global__ __launch_bounds__(512) void attnpool_kernel(
    const f16* __restrict__ H, const float* __restrict__ raw,
    const float* __restrict__ b5, const int* __restrict__ lengths,
    float* __restrict__ pooled)
{
    const int seg = blockIdx.x;
    const int t = threadIdx.x;            // 0..511 -> dims 2t, 2t+1
    const float b5v = b5[0];

    __shared__ float red[512];
    __shared__ float wcache[WCAP];

    int start = 0;
    for (int s = 0; s < seg; s++) start += lengths[s];
    const int len = lengths[seg];

    float m = -INFINITY;
    for (int i = t; i < len; i += 512)
        m = fmaxf(m, fmaxf(raw[start + i] + b5v, 0.f));
    red[t] = m; __syncthreads();
    #pragma unroll
    for (int o = 256; o > 0; o >>= 1) {
        if (t < o) red[t] = fmaxf(red[t], red[t + o]);
        __syncthreads();
    }
    m = red[0]; __syncthreads();

    float ds = 0.f;
    for (int i = t; i < len; i += 512) {
        const float w = __expf(fmaxf(raw[start + i] + b5v, 0.f) - m);
        if (i < WCAP) wcache[i] = w;
        ds += w;
    }
    red[t] = ds; __syncthreads();
    #pragma unroll
    for (int o = 256; o > 0; o >>= 1) {
        if (t < o) red[t] += red[t + o];
        __syncthreads();
    }
    const float inv_denom = 1.0f / red[0];

    const uint32_t* __restrict__ hp =
        reinterpret_cast<const uint32_t*>(H + (size_t)start * HID) + t;
    float ax = 0.f, ay = 0.f;
    int i = 0;
    const int len4 = len & ~3;
    for (; i < len4; i += 4) {
        const float w0 = (i + 0 < WCAP) ? wcache[i + 0]
            : __expf(fmaxf(raw[start + i + 0] + b5v, 0.f) - m);
        const float w1 = (i + 1 < WCAP) ? wcache[i + 1]
            : __expf(fmaxf(raw[start + i + 1] + b5v, 0.f) - m);
        const float w2 = (i + 2 < WCAP) ? wcache[i + 2]
            : __expf(fmaxf(raw[start + i + 2] + b5v, 0.f) - m);
        const float w3 = (i + 3 < WCAP) ? wcache[i + 3]
            : __expf(fmaxf(raw[start + i + 3] + b5v, 0.f) - m);
        const uint32_t u0 = hp[(size_t)(i + 0) * 512];
        const uint32_t u1 = hp[(size_t)(i + 1) * 512];
        const uint32_t u2 = hp[(size_t)(i + 2) * 512];
        const uint32_t u3 = hp[(size_t)(i + 3) * 512];
        const __half2 h0 = *reinterpret_cast<const __half2*>(&u0);
        const __half2 h1 = *reinterpret_cast<const __half2*>(&u1);
        const __half2 h2 = *reinterpret_cast<const __half2*>(&u2);
        const __half2 h3 = *reinterpret_cast<const __half2*>(&u3);
        ax = fmaf(w0, __low2float(h0), ax);  ay = fmaf(w0, __high2float(h0), ay);
        ax = fmaf(w1, __low2float(h1), ax);  ay = fmaf(w1, __high2float(h1), ay);
        ax = fmaf(w2, __low2float(h2), ax);  ay = fmaf(w2, __high2float(h2), ay);
        ax = fmaf(w3, __low2float(h3), ax);  ay = fmaf(w3, __high2float(h3), ay);
    }
    for (; i < len; ++i) {
        const float w = (i < WCAP) ? wcache[i]
            : __expf(fmaxf(raw[start + i] + b5v, 0.f) - m);
        const uint32_t u = hp[(size_t)i * 512];
        const __half2 h = *reinterpret_cast<const __half2*>(&u);
        ax = fmaf(w, __low2float(h), ax);
        ay = fmaf(w, __high2float(h), ay);
    }
    pooled[seg * HID + 2 * t]     = ax * inv_denom;
    pooled[seg * HID + 2 * t + 1] = ay * inv_denom;
}

// ----------------------------------------------------------------------------
// fp32 SIMT GEMM for the small head (256x1024 @ 1024x1024)
// ----------------------------------------------------------------------------
#define TILE 64
#define KT   16

__global__ __launch_bounds__(256) void gemm_bias_act_kernel(
    const float* __restrict__ A, const float* __restrict__ B,
    const float* __restrict__ bias, float* __restrict__ C,
    int N, int K, int M, int do_relu)
{
    __shared__ float As[KT][TILE + 1];
    __shared__ float Bs[KT][TILE];

    const int tx = threadIdx.x, ty = threadIdx.y;
    const int tid = ty * 16 + tx;
    const int row0 = blockIdx.y * TILE;
    const int col0 = blockIdx.x * TILE;
    const int ar = tid >> 4, ak = tid & 15;
    const int bc = tid & 63, bk = tid >> 6;

    float acc[4][4];
    #pragma unroll
    for (int i = 0; i < 4; i++)
        #pragma unroll
        for (int j = 0; j < 4; j++) acc[i][j] = 0.f;

    for (int k0 = 0; k0 < K; k0 += KT) {
        #pragma unroll
        for (int q = 0; q < 4; q++) {
            const int r = ar + q * 16;
            const int gk = k0 + ak;
            As[ak][r] = (gk < K) ? A[(size_t)(row0 + r) * K + gk] : 0.f;
        }
        #pragma unroll
        for (int q = 0; q < 4; q++) {
            const int kk = bk + q * 4;
            const int gk = k0 + kk;
            Bs[kk][bc] = (gk < K) ? B[(size_t)gk * M + (col0 + bc)] : 0.f;
        }
        __syncthreads();
        #pragma unroll
        for (int kk = 0; kk < KT; kk++) {
            float a[4];
            #pragma unroll
            for (int i = 0; i < 4; i++) a[i] = As[kk][ty * 4 + i];
            const float4 bv = *reinterpret_cast<const float4*>(&Bs[kk][tx * 4]);
            const float b[4] = {bv.x, bv.y, bv.z, bv.w};
            #pragma unroll
            for (int i = 0; i < 4; i++)
                #pragma unroll
                for (int j = 0; j < 4; j++)
                    acc[i][j] = fmaf(a[i], b[j], acc[i][j]);
        }
        __syncthreads();
    }
    #pragma unroll
    for (int i = 0; i < 4; i++) {
        const int r = row0 + ty * 4 + i;
        #pragma unroll
        for (int j = 0; j < 4; j++) {
            const int c = col0 + tx * 4 + j;
            float v = acc[i][j] + bias[c];
            if (do_relu) v = fmaxf(v, 0.f);
            C[(size_t)r * M + c] = v;
        }
    }
}

__global__ void final_kernel(
    const float* __restrict__ T, const float* __restrict__ W7,
    const float* __restrict__ b7, float* __restrict__ out)
{
    const int row = blockIdx.x;
    const int j = threadIdx.y;
    const int lane = threadIdx.x;
    const float* tr = T + (size_t)row * HID;
    float s = 0.f;
    #pragma unroll 8
    for (int k = lane; k < HID; k += 32) s = fmaf(tr[k], W7[k * NCLS + j], s);
    #pragma unroll
    for (int o = 16; o > 0; o >>= 1) s += __shfl_xor_sync(0xffffffffu, s, o);
    if (lane == 0) out[row * NCLS + j] = s + b7[j];
}

// ----------------------------------------------------------------------------
// Launcher
// ----------------------------------------------------------------------------
extern "C" void kernel_launch(void* const* d_in, const int* in_sizes, int n_in,
                              void* d_out, int out_size)
{
    const float* x  = (const float*)d_in[0];
    const float* W1 = (const float*)d_in[1];
    const float* b1 = (const float*)d_in[2];
    const float* W2 = (const float*)d_in[3];
    const float* b2 = (const float*)d_in[4];
    const float* W3 = (const float*)d_in[5];
    const float* b3 = (const float*)d_in[6];
    const float* W4 = (const float*)d_in[7];
    const float* b4 = (const float*)d_in[8];
    const float* W5 = (const float*)d_in[9];
    const float* b5 = (const float*)d_in[10];
    const float* W6 = (const float*)d_in[11];
    const float* b6 = (const float*)d_in[12];
    const float* W7 = (const float*)d_in[13];
    const float* b7 = (const float*)d_in[14];
    const int* lengths = (const int*)d_in[15];
    float* out = (float*)d_out;

    f16 *xp, *A, *B, *W1t, *Wt;
    float *scores_raw, *pooled, *tmp6;
    cudaGetSymbolAddress((void**)&xp, g_xp);
    cudaGetSymbolAddress((void**)&A,  g_A);
    cudaGetSymbolAddress((void**)&B,  g_B);
    cudaGetSymbolAddress((void**)&W1t, g_W1t);
    cudaGetSymbolAddress((void**)&Wt, g_Wt);
    cudaGetSymbolAddress((void**)&scores_raw, g_scores_raw);
    cudaGetSymbolAddress((void**)&pooled, g_pooled);
    cudaGetSymbolAddress((void**)&tmp6, g_tmp6);

    cudaFuncSetAttribute(gemm_mma_kernel,
                         cudaFuncAttributeMaxDynamicSharedMemorySize, GEMM_SMEM);

    // prep
    convert_x_kernel<<<(TOTAL_N * K1P) / 256, 256>>>(x, xp, scores_raw);
    transpose_w_kernel<<<dim3(HID / 32, K1P / 32), dim3(32, 8)>>>(
        W1, FEAT, K1P, W1t);
    transpose_w_kernel<<<dim3(HID / 32, HID / 32), dim3(32, 8)>>>(
        W2, HID, HID, Wt + 0 * HID * HID);
    transpose_w_kernel<<<dim3(HID / 32, HID / 32), dim3(32, 8)>>>(
        W3, HID, HID, Wt + 1 * HID * HID);
    transpose_w_kernel<<<dim3(HID / 32, HID / 32), dim3(32, 8)>>>(
        W4, HID, HID, Wt + 2 * HID * HID);

    const dim3 gemm_grid(HID / BN, TOTAL_N / BM);   // (8, 1024)

    gemm_mma_kernel<<<gemm_grid, 128, GEMM_SMEM>>>(
        xp, W1t, b1, A, nullptr, nullptr, K1P);
    gemm_mma_kernel<<<gemm_grid, 128, GEMM_SMEM>>>(
        A, Wt + 0 * HID * HID, b2, B, nullptr, nullptr, HID);
    gemm_mma_kernel<<<gemm_grid, 128, GEMM_SMEM>>>(
        B, Wt + 1 * HID * HID, b3, A, nullptr, nullptr, HID);
    gemm_mma_kernel<<<gemm_grid, 128, GEMM_SMEM>>>(
        A, Wt + 2 * HID * HID, b4, B, W5, scores_raw, HID);

    attnpool_kernel<<<NSEG, 512>>>(B, scores_raw, b5, lengths, pooled);

    gemm_bias_act_kernel<<<dim3(HID / TILE, NSEG / TILE), dim3(16, 16)>>>(
        pooled, W6, b6, tmp6, NSEG, HID, HID, 1);
    final_kernel<<<NSEG, dim3(32, NCLS)>>>(tmp6, W7, b7, out);

    (void)in_sizes; (void)n_in; (void)out_size;
}

// round 15
// speedup vs baseline: 1.5895x; 1.5895x over previous
#include <cuda_runtime.h>
#include <cuda_fp16.h>
#include <math.h>
#include <stdint.h>

// ----------------------------------------------------------------------------
// Dnn_with_Attention on sm_103 (family-generic: mma.sync HMMA path).
// Pure fp16 operands, fp32 accumulate. 128x128 CTA tile, 64x64 warp tiles,
// 4 warps / 128 threads per CTA, 2 CTAs/SM, BKC=64, 3-stage cp.async.
// R15: R13 mainloop (row-sliced coalesced quarter loads, one commit/chunk)
// with load_quarter issued FIRST in each k16 slice for extra lead time.
// (R14's k-column slicing destroyed global coalescing — reverted.)
// W5 attention-logit GEMV fused into layer-4 epilogue.
// ----------------------------------------------------------------------------

#define TOTAL_N 131072
#define HID     1024
#define FEAT    78
#define K1P     128
#define NSEG    256
#define NCLS    10

#define BM 128
#define BN 128
#define BKC 64                        // K elems per chunk (128 bytes/row)
#define STAGES 3
#define ROWB 144                      // 128B data + 16B pad (conflict-free)
#define A_BYTES (BM * ROWB)           // 18432
#define B_BYTES (BN * ROWB)           // 18432
#define STAGE_BYTES (A_BYTES + B_BYTES)        // 36864
#define GEMM_SMEM (STAGES * STAGE_BYTES)       // 110592

typedef __half f16;

// ------------------------------- scratch -----------------------------------
__device__ f16 g_xp[(size_t)TOTAL_N * K1P];
__device__ f16 g_A[(size_t)TOTAL_N * HID];
__device__ f16 g_B[(size_t)TOTAL_N * HID];
__device__ f16 g_W1t[HID * K1P];
__device__ f16 g_Wt[3][HID * HID];
__device__ float g_scores_raw[TOTAL_N];
__device__ float g_pooled[NSEG * HID];
__device__ float g_tmp6[NSEG * HID];

// ------------------------------ helpers ------------------------------------
__device__ __forceinline__ uint32_t smem_u32(const void* p) {
    uint32_t a;
    asm("{ .reg .u64 t; cvta.to.shared.u64 t, %1; cvt.u32.u64 %0, t; }"
        : "=r"(a) : "l"(p));
    return a;
}
__device__ __forceinline__ void cp16(uint32_t dst, const void* src) {
    asm volatile("cp.async.cg.shared.global [%0], [%1], 16;"
                 :: "r"(dst), "l"(src) : "memory");
}
__device__ __forceinline__ void cp_commit() {
    asm volatile("cp.async.commit_group;" ::: "memory");
}
template <int N>
__device__ __forceinline__ void cp_wait() {
    asm volatile("cp.async.wait_group %0;" :: "n"(N) : "memory");
}
__device__ __forceinline__ void ldmx4(uint32_t* r, uint32_t addr) {
    asm volatile("ldmatrix.sync.aligned.m8n8.x4.shared.b16 {%0,%1,%2,%3}, [%4];"
                 : "=r"(r[0]), "=r"(r[1]), "=r"(r[2]), "=r"(r[3]) : "r"(addr));
}
__device__ __forceinline__ void mma_f16(float* c, const uint32_t* a,
                                        const uint32_t* b) {
    asm volatile(
        "mma.sync.aligned.m16n8k16.row.col.f32.f16.f16.f32 "
        "{%0,%1,%2,%3}, {%4,%5,%6,%7}, {%8,%9}, {%0,%1,%2,%3};"
        : "+f"(c[0]), "+f"(c[1]), "+f"(c[2]), "+f"(c[3])
        : "r"(a[0]), "r"(a[1]), "r"(a[2]), "r"(a[3]), "r"(b[0]), "r"(b[1]));
}

// ----------------------------------------------------------------------------
// HMMA GEMM: C[M,1024] = relu(A[M,K] @ Bt[1024,K]^T + bias), fp16 in, fp32 acc.
// Optional fused W5 dots -> atomicAdd(scores_raw) (layer 4).
// grid = (1024/BN, M/BM), block = 128 (4 warps, each 64x64), 2 CTAs/SM.
// ----------------------------------------------------------------------------
__global__ void __launch_bounds__(128, 2) gemm_mma_kernel(
    const f16* __restrict__ A, const f16* __restrict__ Bt,
    const float* __restrict__ bias, f16* __restrict__ C,
    const float* __restrict__ W5, float* __restrict__ scores_raw,
    int K)
{
    extern __shared__ char smem[];
    const uint32_t sbase = smem_u32(smem);
    const int tid = threadIdx.x;
    const int lane = tid & 31;
    const int wid = tid >> 5;
    const int wm = (wid >> 1) * 64;    // 2 warps over m
    const int wn = (wid & 1) * 64;     // 2 warps over n
    const int m0 = blockIdx.y * BM;
    const int n0 = blockIdx.x * BN;
    const int NC = K / BKC;

    // ldmatrix lane-address components
    const int a_row = lane & 15;
    const int a_kb  = (lane >> 4) * 16;
    const int b_row = (lane & 7) + 8 * (lane >> 4);
    const int b_kb  = ((lane >> 3) & 1) * 16;

    float acc[4][8][4];
    #pragma unroll
    for (int i = 0; i < 4; i++)
        #pragma unroll
        for (int j = 0; j < 8; j++)
            #pragma unroll
            for (int q = 0; q < 4; q++) acc[i][j][q] = 0.f;

    // full-chunk loader (prologue only): A 1024 + B 1024 transfers, 16/thread
    auto load_chunk = [&](int stage, int kc) {
        const uint32_t sd = sbase + stage * STAGE_BYTES;
        const int k0 = kc * BKC;
        #pragma unroll
        for (int j = 0; j < 8; ++j) {
            const int idx = tid + 128 * j;     // 0..1023
            const int r = idx >> 3;
            const int c16 = idx & 7;
            cp16(sd + r * ROWB + c16 * 16,
                 A + (size_t)(m0 + r) * K + k0 + c16 * 8);
        }
        #pragma unroll
        for (int j = 0; j < 8; ++j) {
            const int idx = tid + 128 * j;
            const int r = idx >> 3;
            const int c16 = idx & 7;
            cp16(sd + A_BYTES + r * ROWB + c16 * 16,
                 Bt + (size_t)(n0 + r) * K + k0 + c16 * 8);
        }
    };

    // quarter-chunk loader: slice q in [0,4) issues 2 A + 2 B transfers/thread
    // (row-sliced: 8 consecutive threads cover one contiguous 128B row — coalesced)
    auto load_quarter = [&](int stage, int kc, int q) {
        const uint32_t sd = sbase + stage * STAGE_BYTES;
        const int k0 = kc * BKC;
        #pragma unroll
        for (int jj = 0; jj < 2; ++jj) {
            const int j = q * 2 + jj;          // 0..7
            const int idx = tid + 128 * j;
            const int r = idx >> 3;
            const int c16 = idx & 7;
            cp16(sd + r * ROWB + c16 * 16,
                 A + (size_t)(m0 + r) * K + k0 + c16 * 8);
            cp16(sd + A_BYTES + r * ROWB + c16 * 16,
                 Bt + (size_t)(n0 + r) * K + k0 + c16 * 8);
        }
    };

    #pragma unroll
    for (int c = 0; c < STAGES - 1; ++c) {
        if (c < NC) load_chunk(c, c);
        cp_commit();
    }

    for (int c = 0; c < NC; ++c) {
        cp_wait<STAGES - 2>();
        __syncthreads();

        const int lc = c + STAGES - 1;
        const int lstage = lc % STAGES;
        const bool do_load = (lc < NC);

        const uint32_t st = sbase + (c % STAGES) * STAGE_BYTES;
        #pragma unroll
        for (int k16 = 0; k16 < 4; ++k16) {
            const int xb = k16 * 32;
            // issue next-chunk global loads for this slice FIRST (max lead time)
            if (do_load) load_quarter(lstage, lc, k16);
            uint32_t a[4][4], b[8][2];
            #pragma unroll
            for (int mf = 0; mf < 4; ++mf)
                ldmx4(a[mf], st + (wm + mf * 16 + a_row) * ROWB + xb + a_kb);
            #pragma unroll
            for (int p = 0; p < 4; ++p) {
                uint32_t r[4];
                ldmx4(r, st + A_BYTES +
                          (wn + p * 16 + b_row) * ROWB + xb + b_kb);
                b[p * 2][0] = r[0]; b[p * 2][1] = r[1];
                b[p * 2 + 1][0] = r[2]; b[p * 2 + 1][1] = r[3];
            }
            #pragma unroll
            for (int mf = 0; mf < 4; ++mf)
                #pragma unroll
                for (int nf = 0; nf < 8; ++nf)
                    mma_f16(acc[mf][nf], a[mf], b[nf]);
        }
        cp_commit();
    }

    // epilogue: bias + relu + fp16 store (+ fused W5 dot)
    const int gr = lane >> 2;
    float sdot[4][2];
    #pragma unroll
    for (int mf = 0; mf < 4; ++mf) { sdot[mf][0] = 0.f; sdot[mf][1] = 0.f; }

    #pragma unroll
    for (int mf = 0; mf < 4; ++mf) {
        const int r0 = m0 + wm + mf * 16 + gr;
        #pragma unroll
        for (int nf = 0; nf < 8; ++nf) {
            const int c0 = n0 + wn + nf * 8 + (lane & 3) * 2;
            const float bv0 = bias[c0], bv1 = bias[c0 + 1];
            const float v00 = fmaxf(acc[mf][nf][0] + bv0, 0.f);
            const float v01 = fmaxf(acc[mf][nf][1] + bv1, 0.f);
            const float v10 = fmaxf(acc[mf][nf][2] + bv0, 0.f);
            const float v11 = fmaxf(acc[mf][nf][3] + bv1, 0.f);

            if (W5 != nullptr) {
                const float w0 = W5[c0], w1 = W5[c0 + 1];
                sdot[mf][0] = fmaf(v00, w0, fmaf(v01, w1, sdot[mf][0]));
                sdot[mf][1] = fmaf(v10, w0, fmaf(v11, w1, sdot[mf][1]));
            }

            const uint32_t p0 =
                ((uint32_t)__half_as_ushort(__float2half(v01)) << 16) |
                __half_as_ushort(__float2half(v00));
            const uint32_t p1 =
                ((uint32_t)__half_as_ushort(__float2half(v11)) << 16) |
                __half_as_ushort(__float2half(v10));
            *reinterpret_cast<uint32_t*>(C + (size_t)r0 * HID + c0) = p0;
            *reinterpret_cast<uint32_t*>(C + (size_t)(r0 + 8) * HID + c0) = p1;
        }
    }

    if (W5 != nullptr) {
        #pragma unroll
        for (int mf = 0; mf < 4; ++mf) {
            float s0 = sdot[mf][0], s1 = sdot[mf][1];
            s0 += __shfl_xor_sync(0xffffffffu, s0, 1);
            s0 += __shfl_xor_sync(0xffffffffu, s0, 2);
            s1 += __shfl_xor_sync(0xffffffffu, s1, 1);
            s1 += __shfl_xor_sync(0xffffffffu, s1, 2);
            if ((lane & 3) == 0) {
                const int r0 = m0 + wm + mf * 16 + gr;
                atomicAdd(&scores_raw[r0], s0);
                atomicAdd(&scores_raw[r0 + 8], s1);
            }
        }
    }
}

// ----------------------------------------------------------------------------
// Prep kernels (convert_x also zeroes scores_raw)
// ----------------------------------------------------------------------------
__global__ __launch_bounds__(256) void convert_x_kernel(
    const float* __restrict__ x, f16* __restrict__ xp,
    float* __restrict__ scores_raw)
{
    const size_t idx = (size_t)blockIdx.x * 256 + threadIdx.x;
    const int row = (int)(idx >> 7);
    const int k = (int)(idx & 127);
    xp[idx] = __float2half((k < FEAT) ? x[(size_t)row * FEAT + k] : 0.f);
    if (k == 0) scores_raw[row] = 0.f;
}

__global__ __launch_bounds__(256) void transpose_w_kernel(
    const float* __restrict__ W, int Kin, int Kpad, f16* __restrict__ Wt)
{
    __shared__ float t[32][33];
    const int n0 = blockIdx.x * 32;
    const int k0 = blockIdx.y * 32;
    #pragma unroll
    for (int r = 0; r < 4; ++r) {
        const int k = k0 + threadIdx.y + r * 8;
        t[threadIdx.y + r * 8][threadIdx.x] =
            (k < Kin) ? W[(size_t)k * HID + n0 + threadIdx.x] : 0.f;
    }
    __syncthreads();
    #pragma unroll
    for (int r = 0; r < 4; ++r) {
        const int n = n0 + threadIdx.y + r * 8;
        const int k = k0 + threadIdx.x;
        Wt[(size_t)n * Kpad + k] = __float2half(t[threadIdx.x][threadIdx.y + r * 8]);
    }
}

// ----------------------------------------------------------------------------
// Ragged segment softmax + weighted pooling. score_i = relu(raw_i + b5).
// One block per segment, 512 threads, 2 dims/thread (half2), smem weight cache.
// ----------------------------------------------------------------------------
#define WCAP 2048

__global__ __launch_bounds__(512) void attnpool_kernel(
    const f16* __restrict__ H, const float* __restrict__ raw,
    const float* __restrict__ b5, const int* __restrict__ lengths,
    float* __restrict__ pooled)
{
    const int seg = blockIdx.x;
    const int t = threadIdx.x;            // 0..511 -> dims 2t, 2t+1
    const float b5v = b5[0];

    __shared__ float red[512];
    __shared__ float wcache[WCAP];

    int start = 0;
    for (int s = 0; s < seg; s++) start += lengths[s];
    const int len = lengths[seg];

    float m = -INFINITY;
    for (int i = t; i < len; i += 512)
        m = fmaxf(m, fmaxf(raw[start + i] + b5v, 0.f));
    red[t] = m; __syncthreads();
    #pragma unroll
    for (int o = 256; o > 0; o >>= 1) {
        if (t < o) red[t] = fmaxf(red[t], red[t + o]);
        __syncthreads();
    }
    m = red[0]; __syncthreads();

    float ds = 0.f;
    for (int i = t; i < len; i += 512) {
        const float w = __expf(fmaxf(raw[start + i] + b5v, 0.f) - m);
        if (i < WCAP) wcache[i] = w;
        ds += w;
    }
    red[t] = ds; __syncthreads();
    #pragma unroll
    for (int o = 256; o > 0; o >>= 1) {
        if (t < o) red[t] += red[t + o];
        __syncthreads();
    }
    const float inv_denom = 1.0f / red[0];

    const uint32_t* __restrict__ hp =
        reinterpret_cast<const uint32_t*>(H + (size_t)start * HID) + t;
    float ax = 0.f, ay = 0.f;
    int i = 0;
    const int len4 = len & ~3;
    for (; i < len4; i += 4) {
        const float w0 = (i + 0 < WCAP) ? wcache[i + 0]
            : __expf(fmaxf(raw[start + i + 0] + b5v, 0.f) - m);
        const float w1 = (i + 1 < WCAP) ? wcache[i + 1]
            : __expf(fmaxf(raw[start + i + 1] + b5v, 0.f) - m);
        const float w2 = (i + 2 < WCAP) ? wcache[i + 2]
            : __expf(fmaxf(raw[start + i + 2] + b5v, 0.f) - m);
        const float w3 = (i + 3 < WCAP) ? wcache[i + 3]
            : __expf(fmaxf(raw[start + i + 3] + b5v, 0.f) - m);
        const uint32_t u0 = hp[(size_t)(i + 0) * 512];
        const uint32_t u1 = hp[(size_t)(i + 1) * 512];
        const uint32_t u2 = hp[(size_t)(i + 2) * 512];
        const uint32_t u3 = hp[(size_t)(i + 3) * 512];
        const __half2 h0 = *reinterpret_cast<const __half2*>(&u0);
        const __half2 h1 = *reinterpret_cast<const __half2*>(&u1);
        const __half2 h2 = *reinterpret_cast<const __half2*>(&u2);
        const __half2 h3 = *reinterpret_cast<const __half2*>(&u3);
        ax = fmaf(w0, __low2float(h0), ax);  ay = fmaf(w0, __high2float(h0), ay);
        ax = fmaf(w1, __low2float(h1), ax);  ay = fmaf(w1, __high2float(h1), ay);
        ax = fmaf(w2, __low2float(h2), ax);  ay = fmaf(w2, __high2float(h2), ay);
        ax = fmaf(w3, __low2float(h3), ax);  ay = fmaf(w3, __high2float(h3), ay);
    }
    for (; i < len; ++i) {
        const float w = (i < WCAP) ? wcache[i]
            : __expf(fmaxf(raw[start + i] + b5v, 0.f) - m);
        const uint32_t u = hp[(size_t)i * 512];
        const __half2 h = *reinterpret_cast<const __half2*>(&u);
        ax = fmaf(w, __low2float(h), ax);
        ay = fmaf(w, __high2float(h), ay);
    }
    pooled[seg * HID + 2 * t]     = ax * inv_denom;
    pooled[seg * HID + 2 * t + 1] = ay * inv_denom;
}

// ----------------------------------------------------------------------------
// fp32 SIMT GEMM for the small head (256x1024 @ 1024x1024)
// ----------------------------------------------------------------------------
#define TILE 64
#define KT   16

__global__ __launch_bounds__(256) void gemm_bias_act_kernel(
    const float* __restrict__ A, const float* __restrict__ B,
    const float* __restrict__ bias, float* __restrict__ C,
    int N, int K, int M, int do_relu)
{
    __shared__ float As[KT][TILE + 1];
    __shared__ float Bs[KT][TILE];

    const int tx = threadIdx.x, ty = threadIdx.y;
    const int tid = ty * 16 + tx;
    const int row0 = blockIdx.y * TILE;
    const int col0 = blockIdx.x * TILE;
    const int ar = tid >> 4, ak = tid & 15;
    const int bc = tid & 63, bk = tid >> 6;

    float acc[4][4];
    #pragma unroll
    for (int i = 0; i < 4; i++)
        #pragma unroll
        for (int j = 0; j < 4; j++) acc[i][j] = 0.f;

    for (int k0 = 0; k0 < K; k0 += KT) {
        #pragma unroll
        for (int q = 0; q < 4; q++) {
            const int r = ar + q * 16;
            const int gk = k0 + ak;
            As[ak][r] = (gk < K) ? A[(size_t)(row0 + r) * K + gk] : 0.f;
        }
        #pragma unroll
        for (int q = 0; q < 4; q++) {
            const int kk = bk + q * 4;
            const int gk = k0 + kk;
            Bs[kk][bc] = (gk < K) ? B[(size_t)gk * M + (col0 + bc)] : 0.f;
        }
        __syncthreads();
        #pragma unroll
        for (int kk = 0; kk < KT; kk++) {
            float a[4];
            #pragma unroll
            for (int i = 0; i < 4; i++) a[i] = As[kk][ty * 4 + i];
            const float4 bv = *reinterpret_cast<const float4*>(&Bs[kk][tx * 4]);
            const float b[4] = {bv.x, bv.y, bv.z, bv.w};
            #pragma unroll
            for (int i = 0; i < 4; i++)
                #pragma unroll
                for (int j = 0; j < 4; j++)
                    acc[i][j] = fmaf(a[i], b[j], acc[i][j]);
        }
        __syncthreads();
    }
    #pragma unroll
    for (int i = 0; i < 4; i++) {
        const int r = row0 + ty * 4 + i;
        #pragma unroll
        for (int j = 0; j < 4; j++) {
            const int c = col0 + tx * 4 + j;
            float v = acc[i][j] + bias[c];
            if (do_relu) v = fmaxf(v, 0.f);
            C[(size_t)r * M + c] = v;
        }
    }
}

__global__ void final_kernel(
    const float* __restrict__ T, const float* __restrict__ W7,
    const float* __restrict__ b7, float* __restrict__ out)
{
    const int row = blockIdx.x;
    const int j = threadIdx.y;
    const int lane = threadIdx.x;
    const float* tr = T + (size_t)row * HID;
    float s = 0.f;
    #pragma unroll 8
    for (int k = lane; k < HID; k += 32) s = fmaf(tr[k], W7[k * NCLS + j], s);
    #pragma unroll
    for (int o = 16; o > 0; o >>= 1) s += __shfl_xor_sync(0xffffffffu, s, o);
    if (lane == 0) out[row * NCLS + j] = s + b7[j];
}

// ----------------------------------------------------------------------------
// Launcher
// ----------------------------------------------------------------------------
extern "C" void kernel_launch(void* const* d_in, const int* in_sizes, int n_in,
                              void* d_out, int out_size)
{
    const float* x  = (const float*)d_in[0];
    const float* W1 = (const float*)d_in[1];
    const float* b1 = (const float*)d_in[2];
    const float* W2 = (const float*)d_in[3];
    const float* b2 = (const float*)d_in[4];
    const float* W3 = (const float*)d_in[5];
    const float* b3 = (const float*)d_in[6];
    const float* W4 = (const float*)d_in[7];
    const float* b4 = (const float*)d_in[8];
    const float* W5 = (const float*)d_in[9];
    const float* b5 = (const float*)d_in[10];
    const float* W6 = (const float*)d_in[11];
    const float* b6 = (const float*)d_in[12];
    const float* W7 = (const float*)d_in[13];
    const float* b7 = (const float*)d_in[14];
    const int* lengths = (const int*)d_in[15];
    float* out = (float*)d_out;

    f16 *xp, *A, *B, *W1t, *Wt;
    float *scores_raw, *pooled, *tmp6;
    cudaGetSymbolAddress((void**)&xp, g_xp);
    cudaGetSymbolAddress((void**)&A,  g_A);
    cudaGetSymbolAddress((void**)&B,  g_B);
    cudaGetSymbolAddress((void**)&W1t, g_W1t);
    cudaGetSymbolAddress((void**)&Wt, g_Wt);
    cudaGetSymbolAddress((void**)&scores_raw, g_scores_raw);
    cudaGetSymbolAddress((void**)&pooled, g_pooled);
    cudaGetSymbolAddress((void**)&tmp6, g_tmp6);

    cudaFuncSetAttribute(gemm_mma_kernel,
                         cudaFuncAttributeMaxDynamicSharedMemorySize, GEMM_SMEM);

    // prep
    convert_x_kernel<<<(TOTAL_N * K1P) / 256, 256>>>(x, xp, scores_raw);
    transpose_w_kernel<<<dim3(HID / 32, K1P / 32), dim3(32, 8)>>>(
        W1, FEAT, K1P, W1t);
    transpose_w_kernel<<<dim3(HID / 32, HID / 32), dim3(32, 8)>>>(
        W2, HID, HID, Wt + 0 * HID * HID);
    transpose_w_kernel<<<dim3(HID / 32, HID / 32), dim3(32, 8)>>>(
        W3, HID, HID, Wt + 1 * HID * HID);
    transpose_w_kernel<<<dim3(HID / 32, HID / 32), dim3(32, 8)>>>(
        W4, HID, HID, Wt + 2 * HID * HID);

    const dim3 gemm_grid(HID / BN, TOTAL_N / BM);   // (8, 1024)

    gemm_mma_kernel<<<gemm_grid, 128, GEMM_SMEM>>>(
        xp, W1t, b1, A, nullptr, nullptr, K1P);
    gemm_mma_kernel<<<gemm_grid, 128, GEMM_SMEM>>>(
        A, Wt + 0 * HID * HID, b2, B, nullptr, nullptr, HID);
    gemm_mma_kernel<<<gemm_grid, 128, GEMM_SMEM>>>(
        B, Wt + 1 * HID * HID, b3, A, nullptr, nullptr, HID);
    gemm_mma_kernel<<<gemm_grid, 128, GEMM_SMEM>>>(
        A, Wt + 2 * HID * HID, b4, B, W5, scores_raw, HID);

    attnpool_kernel<<<NSEG, 512>>>(B, scores_raw, b5, lengths, pooled);

    gemm_bias_act_kernel<<<dim3(HID / TILE, NSEG / TILE), dim3(16, 16)>>>(
        pooled, W6, b6, tmp6, NSEG, HID, HID, 1);
    final_kernel<<<NSEG, dim3(32, NCLS)>>>(tmp6, W7, b7, out);

    (void)in_sizes; (void)n_in; (void)out_size;
}

// round 16
// speedup vs baseline: 1.5934x; 1.0025x over previous
#include <cuda_runtime.h>
#include <cuda_fp16.h>
#include <math.h>
#include <stdint.h>

// ----------------------------------------------------------------------------
// Dnn_with_Attention on sm_103 (family-generic: mma.sync HMMA path).
// Pure fp16 operands, fp32 accumulate. 128x128 CTA tile, 64x64 warp tiles,
// 4 warps / 128 threads per CTA, 2 CTAs/SM, BKC=64, 3-stage cp.async with
// quarter-loads distributed through the k16 loop (R13 winner, bit-exact).
// R16: outer-loop unroll(1) for I$ residency + batched weight transpose.
// W5 attention-logit GEMV fused into layer-4 epilogue.
// ----------------------------------------------------------------------------

#define TOTAL_N 131072
#define HID     1024
#define FEAT    78
#define K1P     128
#define NSEG    256
#define NCLS    10

#define BM 128
#define BN 128
#define BKC 64                        // K elems per chunk (128 bytes/row)
#define STAGES 3
#define ROWB 144                      // 128B data + 16B pad (conflict-free)
#define A_BYTES (BM * ROWB)           // 18432
#define B_BYTES (BN * ROWB)           // 18432
#define STAGE_BYTES (A_BYTES + B_BYTES)        // 36864
#define GEMM_SMEM (STAGES * STAGE_BYTES)       // 110592

typedef __half f16;

// ------------------------------- scratch -----------------------------------
__device__ f16 g_xp[(size_t)TOTAL_N * K1P];
__device__ f16 g_A[(size_t)TOTAL_N * HID];
__device__ f16 g_B[(size_t)TOTAL_N * HID];
__device__ f16 g_W1t[HID * K1P];
__device__ f16 g_Wt[3][HID * HID];
__device__ float g_scores_raw[TOTAL_N];
__device__ float g_pooled[NSEG * HID];
__device__ float g_tmp6[NSEG * HID];

// ------------------------------ helpers ------------------------------------
__device__ __forceinline__ uint32_t smem_u32(const void* p) {
    uint32_t a;
    asm("{ .reg .u64 t; cvta.to.shared.u64 t, %1; cvt.u32.u64 %0, t; }"
        : "=r"(a) : "l"(p));
    return a;
}
__device__ __forceinline__ void cp16(uint32_t dst, const void* src) {
    asm volatile("cp.async.cg.shared.global [%0], [%1], 16;"
                 :: "r"(dst), "l"(src) : "memory");
}
__device__ __forceinline__ void cp_commit() {
    asm volatile("cp.async.commit_group;" ::: "memory");
}
template <int N>
__device__ __forceinline__ void cp_wait() {
    asm volatile("cp.async.wait_group %0;" :: "n"(N) : "memory");
}
__device__ __forceinline__ void ldmx4(uint32_t* r, uint32_t addr) {
    asm volatile("ldmatrix.sync.aligned.m8n8.x4.shared.b16 {%0,%1,%2,%3}, [%4];"
                 : "=r"(r[0]), "=r"(r[1]), "=r"(r[2]), "=r"(r[3]) : "r"(addr));
}
__device__ __forceinline__ void mma_f16(float* c, const uint32_t* a,
                                        const uint32_t* b) {
    asm volatile(
        "mma.sync.aligned.m16n8k16.row.col.f32.f16.f16.f32 "
        "{%0,%1,%2,%3}, {%4,%5,%6,%7}, {%8,%9}, {%0,%1,%2,%3};"
        : "+f"(c[0]), "+f"(c[1]), "+f"(c[2]), "+f"(c[3])
        : "r"(a[0]), "r"(a[1]), "r"(a[2]), "r"(a[3]), "r"(b[0]), "r"(b[1]));
}

// ----------------------------------------------------------------------------
// HMMA GEMM: C[M,1024] = relu(A[M,K] @ Bt[1024,K]^T + bias), fp16 in, fp32 acc.
// Optional fused W5 dots -> atomicAdd(scores_raw) (layer 4).
// grid = (1024/BN, M/BM), block = 128 (4 warps, each 64x64), 2 CTAs/SM.
// ----------------------------------------------------------------------------
__global__ void __launch_bounds__(128, 2) gemm_mma_kernel(
    const f16* __restrict__ A, const f16* __restrict__ Bt,
    const float* __restrict__ bias, f16* __restrict__ C,
    const float* __restrict__ W5, float* __restrict__ scores_raw,
    int K)
{
    extern __shared__ char smem[];
    const uint32_t sbase = smem_u32(smem);
    const int tid = threadIdx.x;
    const int lane = tid & 31;
    const int wid = tid >> 5;
    const int wm = (wid >> 1) * 64;    // 2 warps over m
    const int wn = (wid & 1) * 64;     // 2 warps over n
    const int m0 = blockIdx.y * BM;
    const int n0 = blockIdx.x * BN;
    const int NC = K / BKC;

    // ldmatrix lane-address components
    const int a_row = lane & 15;
    const int a_kb  = (lane >> 4) * 16;
    const int b_row = (lane & 7) + 8 * (lane >> 4);
    const int b_kb  = ((lane >> 3) & 1) * 16;

    float acc[4][8][4];
    #pragma unroll
    for (int i = 0; i < 4; i++)
        #pragma unroll
        for (int j = 0; j < 8; j++)
            #pragma unroll
            for (int q = 0; q < 4; q++) acc[i][j][q] = 0.f;

    // full-chunk loader (prologue only): A 1024 + B 1024 transfers, 16/thread
    auto load_chunk = [&](int stage, int kc) {
        const uint32_t sd = sbase + stage * STAGE_BYTES;
        const int k0 = kc * BKC;
        #pragma unroll
        for (int j = 0; j < 8; ++j) {
            const int idx = tid + 128 * j;     // 0..1023
            const int r = idx >> 3;
            const int c16 = idx & 7;
            cp16(sd + r * ROWB + c16 * 16,
                 A + (size_t)(m0 + r) * K + k0 + c16 * 8);
        }
        #pragma unroll
        for (int j = 0; j < 8; ++j) {
            const int idx = tid + 128 * j;
            const int r = idx >> 3;
            const int c16 = idx & 7;
            cp16(sd + A_BYTES + r * ROWB + c16 * 16,
                 Bt + (size_t)(n0 + r) * K + k0 + c16 * 8);
        }
    };

    // quarter-chunk loader: slice q in [0,4) issues 2 A + 2 B transfers/thread
    // (row-sliced: 8 consecutive threads cover one contiguous 128B row)
    auto load_quarter = [&](int stage, int kc, int q) {
        const uint32_t sd = sbase + stage * STAGE_BYTES;
        const int k0 = kc * BKC;
        #pragma unroll
        for (int jj = 0; jj < 2; ++jj) {
            const int j = q * 2 + jj;          // 0..7
            const int idx = tid + 128 * j;
            const int r = idx >> 3;
            const int c16 = idx & 7;
            cp16(sd + r * ROWB + c16 * 16,
                 A + (size_t)(m0 + r) * K + k0 + c16 * 8);
            cp16(sd + A_BYTES + r * ROWB + c16 * 16,
                 Bt + (size_t)(n0 + r) * K + k0 + c16 * 8);
        }
    };

    #pragma unroll
    for (int c = 0; c < STAGES - 1; ++c) {
        if (c < NC) load_chunk(c, c);
        cp_commit();
    }

    #pragma unroll 1
    for (int c = 0; c < NC; ++c) {
        cp_wait<STAGES - 2>();
        __syncthreads();

        const int lc = c + STAGES - 1;
        const int lstage = lc % STAGES;
        const bool do_load = (lc < NC);

        const uint32_t st = sbase + (c % STAGES) * STAGE_BYTES;
        #pragma unroll
        for (int k16 = 0; k16 < 4; ++k16) {
            const int xb = k16 * 32;
            uint32_t a[4][4], b[8][2];
            #pragma unroll
            for (int mf = 0; mf < 4; ++mf)
                ldmx4(a[mf], st + (wm + mf * 16 + a_row) * ROWB + xb + a_kb);
            #pragma unroll
            for (int p = 0; p < 4; ++p) {
                uint32_t r[4];
                ldmx4(r, st + A_BYTES +
                          (wn + p * 16 + b_row) * ROWB + xb + b_kb);
                b[p * 2][0] = r[0]; b[p * 2][1] = r[1];
                b[p * 2 + 1][0] = r[2]; b[p * 2 + 1][1] = r[3];
            }
            // spread next-chunk global loads across the 4 slices
            if (do_load) load_quarter(lstage, lc, k16);
            #pragma unroll
            for (int mf = 0; mf < 4; ++mf)
                #pragma unroll
                for (int nf = 0; nf < 8; ++nf)
                    mma_f16(acc[mf][nf], a[mf], b[nf]);
        }
        cp_commit();
    }

    // epilogue: bias + relu + fp16 store (+ fused W5 dot)
    const int gr = lane >> 2;
    float sdot[4][2];
    #pragma unroll
    for (int mf = 0; mf < 4; ++mf) { sdot[mf][0] = 0.f; sdot[mf][1] = 0.f; }

    #pragma unroll
    for (int mf = 0; mf < 4; ++mf) {
        const int r0 = m0 + wm + mf * 16 + gr;
        #pragma unroll
        for (int nf = 0; nf < 8; ++nf) {
            const int c0 = n0 + wn + nf * 8 + (lane & 3) * 2;
            const float bv0 = bias[c0], bv1 = bias[c0 + 1];
            const float v00 = fmaxf(acc[mf][nf][0] + bv0, 0.f);
            const float v01 = fmaxf(acc[mf][nf][1] + bv1, 0.f);
            const float v10 = fmaxf(acc[mf][nf][2] + bv0, 0.f);
            const float v11 = fmaxf(acc[mf][nf][3] + bv1, 0.f);

            if (W5 != nullptr) {
                const float w0 = W5[c0], w1 = W5[c0 + 1];
                sdot[mf][0] = fmaf(v00, w0, fmaf(v01, w1, sdot[mf][0]));
                sdot[mf][1] = fmaf(v10, w0, fmaf(v11, w1, sdot[mf][1]));
            }

            const uint32_t p0 =
                ((uint32_t)__half_as_ushort(__float2half(v01)) << 16) |
                __half_as_ushort(__float2half(v00));
            const uint32_t p1 =
                ((uint32_t)__half_as_ushort(__float2half(v11)) << 16) |
                __half_as_ushort(__float2half(v10));
            *reinterpret_cast<uint32_t*>(C + (size_t)r0 * HID + c0) = p0;
            *reinterpret_cast<uint32_t*>(C + (size_t)(r0 + 8) * HID + c0) = p1;
        }
    }

    if (W5 != nullptr) {
        #pragma unroll
        for (int mf = 0; mf < 4; ++mf) {
            float s0 = sdot[mf][0], s1 = sdot[mf][1];
            s0 += __shfl_xor_sync(0xffffffffu, s0, 1);
            s0 += __shfl_xor_sync(0xffffffffu, s0, 2);
            s1 += __shfl_xor_sync(0xffffffffu, s1, 1);
            s1 += __shfl_xor_sync(0xffffffffu, s1, 2);
            if ((lane & 3) == 0) {
                const int r0 = m0 + wm + mf * 16 + gr;
                atomicAdd(&scores_raw[r0], s0);
                atomicAdd(&scores_raw[r0 + 8], s1);
            }
        }
    }
}

// ----------------------------------------------------------------------------
// Prep kernels (convert_x also zeroes scores_raw; mid-layer transposes batched)
// ----------------------------------------------------------------------------
__global__ __launch_bounds__(256) void convert_x_kernel(
    const float* __restrict__ x, f16* __restrict__ xp,
    float* __restrict__ scores_raw)
{
    const size_t idx = (size_t)blockIdx.x * 256 + threadIdx.x;
    const int row = (int)(idx >> 7);
    const int k = (int)(idx & 127);
    xp[idx] = __float2half((k < FEAT) ? x[(size_t)row * FEAT + k] : 0.f);
    if (k == 0) scores_raw[row] = 0.f;
}

__global__ __launch_bounds__(256) void transpose_w_kernel(
    const float* __restrict__ W, int Kin, int Kpad, f16* __restrict__ Wt)
{
    __shared__ float t[32][33];
    const int n0 = blockIdx.x * 32;
    const int k0 = blockIdx.y * 32;
    #pragma unroll
    for (int r = 0; r < 4; ++r) {
        const int k = k0 + threadIdx.y + r * 8;
        t[threadIdx.y + r * 8][threadIdx.x] =
            (k < Kin) ? W[(size_t)k * HID + n0 + threadIdx.x] : 0.f;
    }
    __syncthreads();
    #pragma unroll
    for (int r = 0; r < 4; ++r) {
        const int n = n0 + threadIdx.y + r * 8;
        const int k = k0 + threadIdx.x;
        Wt[(size_t)n * Kpad + k] = __float2half(t[threadIdx.x][threadIdx.y + r * 8]);
    }
}

// Batched square transpose for W2/W3/W4 (blockIdx.z selects the layer)
__global__ __launch_bounds__(256) void transpose_w3_kernel(
    const float* __restrict__ W2, const float* __restrict__ W3,
    const float* __restrict__ W4, f16* __restrict__ Wt)
{
    __shared__ float t[32][33];
    const int layer = blockIdx.z;
    const float* __restrict__ W = (layer == 0) ? W2 : (layer == 1) ? W3 : W4;
    f16* __restrict__ dst = Wt + (size_t)layer * HID * HID;
    const int n0 = blockIdx.x * 32;
    const int k0 = blockIdx.y * 32;
    #pragma unroll
    for (int r = 0; r < 4; ++r) {
        const int k = k0 + threadIdx.y + r * 8;
        t[threadIdx.y + r * 8][threadIdx.x] = W[(size_t)k * HID + n0 + threadIdx.x];
    }
    __syncthreads();
    #pragma unroll
    for (int r = 0; r < 4; ++r) {
        const int n = n0 + threadIdx.y + r * 8;
        const int k = k0 + threadIdx.x;
        dst[(size_t)n * HID + k] = __float2half(t[threadIdx.x][threadIdx.y + r * 8]);
    }
}

// ----------------------------------------------------------------------------
// Ragged segment softmax + weighted pooling. score_i = relu(raw_i + b5).
// One block per segment, 512 threads, 2 dims/thread (half2), smem weight cache.
// ----------------------------------------------------------------------------
#define WCAP 2048

__global__ __launch_bounds__(512) void attnpool_kernel(
    const f16* __restrict__ H, const float* __restrict__ raw,
    const float* __restrict__ b5, const int* __restrict__ lengths,
    float* __restrict__ pooled)
{
    const int seg = blockIdx.x;
    const int t = threadIdx.x;            // 0..511 -> dims 2t, 2t+1
    const float b5v = b5[0];

    __shared__ float red[512];
    __shared__ float wcache[WCAP];

    int start = 0;
    for (int s = 0; s < seg; s++) start += lengths[s];
    const int len = lengths[seg];

    float m = -INFINITY;
    for (int i = t; i < len; i += 512)
        m = fmaxf(m, fmaxf(raw[start + i] + b5v, 0.f));
    red[t] = m; __syncthreads();
    #pragma unroll
    for (int o = 256; o > 0; o >>= 1) {
        if (t < o) red[t] = fmaxf(red[t], red[t + o]);
        __syncthreads();
    }
    m = red[0]; __syncthreads();

    float ds = 0.f;
    for (int i = t; i < len; i += 512) {
        const float w = __expf(fmaxf(raw[start + i] + b5v, 0.f) - m);
        if (i < WCAP) wcache[i] = w;
        ds += w;
    }
    red[t] = ds; __syncthreads();
    #pragma unroll
    for (int o = 256; o > 0; o >>= 1) {
        if (t < o) red[t] += red[t + o];
        __syncthreads();
    }
    const float inv_denom = 1.0f / red[0];

    const uint32_t* __restrict__ hp =
        reinterpret_cast<const uint32_t*>(H + (size_t)start * HID) + t;
    float ax = 0.f, ay = 0.f;
    int i = 0;
    const int len4 = len & ~3;
    for (; i < len4; i += 4) {
        const float w0 = (i + 0 < WCAP) ? wcache[i + 0]
            : __expf(fmaxf(raw[start + i + 0] + b5v, 0.f) - m);
        const float w1 = (i + 1 < WCAP) ? wcache[i + 1]
            : __expf(fmaxf(raw[start + i + 1] + b5v, 0.f) - m);
        const float w2 = (i + 2 < WCAP) ? wcache[i + 2]
            : __expf(fmaxf(raw[start + i + 2] + b5v, 0.f) - m);
        const float w3 = (i + 3 < WCAP) ? wcache[i + 3]
            : __expf(fmaxf(raw[start + i + 3] + b5v, 0.f) - m);
        const uint32_t u0 = hp[(size_t)(i + 0) * 512];
        const uint32_t u1 = hp[(size_t)(i + 1) * 512];
        const uint32_t u2 = hp[(size_t)(i + 2) * 512];
        const uint32_t u3 = hp[(size_t)(i + 3) * 512];
        const __half2 h0 = *reinterpret_cast<const __half2*>(&u0);
        const __half2 h1 = *reinterpret_cast<const __half2*>(&u1);
        const __half2 h2 = *reinterpret_cast<const __half2*>(&u2);
        const __half2 h3 = *reinterpret_cast<const __half2*>(&u3);
        ax = fmaf(w0, __low2float(h0), ax);  ay = fmaf(w0, __high2float(h0), ay);
        ax = fmaf(w1, __low2float(h1), ax);  ay = fmaf(w1, __high2float(h1), ay);
        ax = fmaf(w2, __low2float(h2), ax);  ay = fmaf(w2, __high2float(h2), ay);
        ax = fmaf(w3, __low2float(h3), ax);  ay = fmaf(w3, __high2float(h3), ay);
    }
    for (; i < len; ++i) {
        const float w = (i < WCAP) ? wcache[i]
            : __expf(fmaxf(raw[start + i] + b5v, 0.f) - m);
        const uint32_t u = hp[(size_t)i * 512];
        const __half2 h = *reinterpret_cast<const __half2*>(&u);
        ax = fmaf(w, __low2float(h), ax);
        ay = fmaf(w, __high2float(h), ay);
    }
    pooled[seg * HID + 2 * t]     = ax * inv_denom;
    pooled[seg * HID + 2 * t + 1] = ay * inv_denom;
}

// ----------------------------------------------------------------------------
// fp32 SIMT GEMM for the small head (256x1024 @ 1024x1024)
// ----------------------------------------------------------------------------
#define TILE 64
#define KT   16

__global__ __launch_bounds__(256) void gemm_bias_act_kernel(
    const float* __restrict__ A, const float* __restrict__ B,
    const float* __restrict__ bias, float* __restrict__ C,
    int N, int K, int M, int do_relu)
{
    __shared__ float As[KT][TILE + 1];
    __shared__ float Bs[KT][TILE];

    const int tx = threadIdx.x, ty = threadIdx.y;
    const int tid = ty * 16 + tx;
    const int row0 = blockIdx.y * TILE;
    const int col0 = blockIdx.x * TILE;
    const int ar = tid >> 4, ak = tid & 15;
    const int bc = tid & 63, bk = tid >> 6;

    float acc[4][4];
    #pragma unroll
    for (int i = 0; i < 4; i++)
        #pragma unroll
        for (int j = 0; j < 4; j++) acc[i][j] = 0.f;

    for (int k0 = 0; k0 < K; k0 += KT) {
        #pragma unroll
        for (int q = 0; q < 4; q++) {
            const int r = ar + q * 16;
            const int gk = k0 + ak;
            As[ak][r] = (gk < K) ? A[(size_t)(row0 + r) * K + gk] : 0.f;
        }
        #pragma unroll
        for (int q = 0; q < 4; q++) {
            const int kk = bk + q * 4;
            const int gk = k0 + kk;
            Bs[kk][bc] = (gk < K) ? B[(size_t)gk * M + (col0 + bc)] : 0.f;
        }
        __syncthreads();
        #pragma unroll
        for (int kk = 0; kk < KT; kk++) {
            float a[4];
            #pragma unroll
            for (int i = 0; i < 4; i++) a[i] = As[kk][ty * 4 + i];
            const float4 bv = *reinterpret_cast<const float4*>(&Bs[kk][tx * 4]);
            const float b[4] = {bv.x, bv.y, bv.z, bv.w};
            #pragma unroll
            for (int i = 0; i < 4; i++)
                #pragma unroll
                for (int j = 0; j < 4; j++)
                    acc[i][j] = fmaf(a[i], b[j], acc[i][j]);
        }
        __syncthreads();
    }
    #pragma unroll
    for (int i = 0; i < 4; i++) {
        const int r = row0 + ty * 4 + i;
        #pragma unroll
        for (int j = 0; j < 4; j++) {
            const int c = col0 + tx * 4 + j;
            float v = acc[i][j] + bias[c];
            if (do_relu) v = fmaxf(v, 0.f);
            C[(size_t)r * M + c] = v;
        }
    }
}

__global__ void final_kernel(
    const float* __restrict__ T, const float* __restrict__ W7,
    const float* __restrict__ b7, float* __restrict__ out)
{
    const int row = blockIdx.x;
    const int j = threadIdx.y;
    const int lane = threadIdx.x;
    const float* tr = T + (size_t)row * HID;
    float s = 0.f;
    #pragma unroll 8
    for (int k = lane; k < HID; k += 32) s = fmaf(tr[k], W7[k * NCLS + j], s);
    #pragma unroll
    for (int o = 16; o > 0; o >>= 1) s += __shfl_xor_sync(0xffffffffu, s, o);
    if (lane == 0) out[row * NCLS + j] = s + b7[j];
}

// ----------------------------------------------------------------------------
// Launcher
// ----------------------------------------------------------------------------
extern "C" void kernel_launch(void* const* d_in, const int* in_sizes, int n_in,
                              void* d_out, int out_size)
{
    const float* x  = (const float*)d_in[0];
    const float* W1 = (const float*)d_in[1];
    const float* b1 = (const float*)d_in[2];
    const float* W2 = (const float*)d_in[3];
    const float* b2 = (const float*)d_in[4];
    const float* W3 = (const float*)d_in[5];
    const float* b3 = (const float*)d_in[6];
    const float* W4 = (const float*)d_in[7];
    const float* b4 = (const float*)d_in[8];
    const float* W5 = (const float*)d_in[9];
    const float* b5 = (const float*)d_in[10];
    const float* W6 = (const float*)d_in[11];
    const float* b6 = (const float*)d_in[12];
    const float* W7 = (const float*)d_in[13];
    const float* b7 = (const float*)d_in[14];
    const int* lengths = (const int*)d_in[15];
    float* out = (float*)d_out;

    f16 *xp, *A, *B, *W1t, *Wt;
    float *scores_raw, *pooled, *tmp6;
    cudaGetSymbolAddress((void**)&xp, g_xp);
    cudaGetSymbolAddress((void**)&A,  g_A);
    cudaGetSymbolAddress((void**)&B,  g_B);
    cudaGetSymbolAddress((void**)&W1t, g_W1t);
    cudaGetSymbolAddress((void**)&Wt, g_Wt);
    cudaGetSymbolAddress((void**)&scores_raw, g_scores_raw);
    cudaGetSymbolAddress((void**)&pooled, g_pooled);
    cudaGetSymbolAddress((void**)&tmp6, g_tmp6);

    cudaFuncSetAttribute(gemm_mma_kernel,
                         cudaFuncAttributeMaxDynamicSharedMemorySize, GEMM_SMEM);

    // prep
    convert_x_kernel<<<(TOTAL_N * K1P) / 256, 256>>>(x, xp, scores_raw);
    transpose_w_kernel<<<dim3(HID / 32, K1P / 32), dim3(32, 8)>>>(
        W1, FEAT, K1P, W1t);
    transpose_w3_kernel<<<dim3(HID / 32, HID / 32, 3), dim3(32, 8)>>>(
        W2, W3, W4, Wt);

    const dim3 gemm_grid(HID / BN, TOTAL_N / BM);   // (8, 1024)

    gemm_mma_kernel<<<gemm_grid, 128, GEMM_SMEM>>>(
        xp, W1t, b1, A, nullptr, nullptr, K1P);
    gemm_mma_kernel<<<gemm_grid, 128, GEMM_SMEM>>>(
        A, Wt + 0 * HID * HID, b2, B, nullptr, nullptr, HID);
    gemm_mma_kernel<<<gemm_grid, 128, GEMM_SMEM>>>(
        B, Wt + 1 * HID * HID, b3, A, nullptr, nullptr, HID);
    gemm_mma_kernel<<<gemm_grid, 128, GEMM_SMEM>>>(
        A, Wt + 2 * HID * HID, b4, B, W5, scores_raw, HID);

    attnpool_kernel<<<NSEG, 512>>>(B, scores_raw, b5, lengths, pooled);

    gemm_bias_act_kernel<<<dim3(HID / TILE, NSEG / TILE), dim3(16, 16)>>>(
        pooled, W6, b6, tmp6, NSEG, HID, HID, 1);
    final_kernel<<<NSEG, dim3(32, NCLS)>>>(tmp6, W7, b7, out);

    (void)in_sizes; (void)n_in; (void)out_size;
}